// round 10
// baseline (speedup 1.0000x reference)
#include <cuda_runtime.h>

// Spacial IRNN: 4 directional relu-scans over [B,C,H,W] = [4,64,256,256] fp32.
// out[dir][b][c][h][w], dir: 0=up, 1=right, 2=down, 3=left.
// h_0 = x_edge (raw), h_t = relu(w_c * h_{t-1} + b_c + x_t).
//
// Single-wave layout: 1024 uniform blocks, 7 blocks/SM (smem 32KB via XOR-
// swizzled dense tiles, 36-reg budget via __launch_bounds__(256,7)).
//   role = bid & 1:
//     0 -> vertical block, one direction per block (vb&1: 0=down, 1=up),
//          one thread per column, scalar coalesced I/O, stcs stores.
//     1 -> horizontal block: warp-specialized, threads 0-127 "right" on
//          tile A, 128-255 "left" on tile B, own named barriers; float4 I/O
//          on dense 32-wide tiles with col4 ^= (row&7) swizzle.

#define HH 256
#define WW 256
#define BB 4
#define CC 64

constexpr int HW = HH * WW;
constexpr long long DIRSZ = (long long)BB * CC * HH * WW;  // 16,777,216

constexpr int TPB    = 256;
constexpr int HROWS  = 128;
constexpr int CHUNK  = 32;
constexpr int NCHUNK = WW / CHUNK;              // 8

__device__ __forceinline__ void bar_group(int id) {
    asm volatile("bar.sync %0, 128;" :: "r"(id) : "memory");
}

// float4 slot address within a dense 128x32 tile, XOR-swizzled.
__device__ __forceinline__ int slot(int row, int q) {
    return row * 32 + ((q ^ (row & 7)) << 2);
}

__global__ void __launch_bounds__(TPB, 7)
irnn_fused_kernel(const float* __restrict__ x,
                  const float* __restrict__ w_up,    const float* __restrict__ b_up,
                  const float* __restrict__ w_right, const float* __restrict__ b_right,
                  const float* __restrict__ w_down,  const float* __restrict__ b_down,
                  const float* __restrict__ w_left,  const float* __restrict__ b_left,
                  float* __restrict__ out)
{
    __shared__ float tiles[2][HROWS * 32];   // dense, XOR-swizzled; 32 KB total

    const int bid = blockIdx.x;
    const int tid = threadIdx.x;

    if ((bid & 1) == 0) {
        // ---------------- vertical: one direction, one thread per column ----
        const int vb   = bid >> 1;          // 0 .. 511
        const int isUp = vb & 1;            // 0 = down, 1 = up
        const int unit = vb >> 1;           // 0 .. 255

        const int id = unit * TPB + tid;    // 0 .. B*C*W-1
        const int w  = id & (WW - 1);
        const int bc = id >> 8;
        const int c  = bc & (CC - 1);

        const float* xp = x + (size_t)bc * HW + w;

        if (!isUp) {
            float* od = out + 2 * DIRSZ + (size_t)bc * HW + w;   // down
            const float wd = w_down[c], bd = b_down[c];
            float s = xp[0];
            __stcs(&od[0], s);
#pragma unroll 8
            for (int h = 1; h < HH; ++h) {
                float xv = xp[h * WW];
                s = fmaxf(fmaf(wd, s, bd + xv), 0.0f);
                __stcs(&od[h * WW], s);
            }
        } else {
            float* ou = out + 0 * DIRSZ + (size_t)bc * HW + w;   // up
            const float wu = w_up[c], bu = b_up[c];
            float s = xp[(HH - 1) * WW];
            __stcs(&ou[(HH - 1) * WW], s);
#pragma unroll 8
            for (int h = HH - 2; h >= 0; --h) {
                float xv = xp[h * WW];
                s = fmaxf(fmaf(wu, s, bu + xv), 0.0f);
                __stcs(&ou[h * WW], s);
            }
        }
    } else {
        // ------------------- horizontal: 128 rows, warp-specialized ---------
        const int hb = bid >> 1;                 // 0 .. 511
        const int r0 = hb * HROWS;               // first global row
        const int bc = r0 >> 8;                  // uniform within block
        const int c  = bc & (CC - 1);

        const bool isLeft = (tid >= HROWS);
        const int  gt     = tid & (HROWS - 1);   // thread id within group
        const int  barid  = isLeft ? 2 : 1;

        const float* xbase = x + (size_t)r0 * WW;
        float* obase = out + (isLeft ? 3 : 1) * DIRSZ + (size_t)r0 * WW;

        const float wsc = isLeft ? w_left[c] : w_right[c];
        const float bsc = isLeft ? b_left[c] : b_right[c];

        float* tile = &tiles[isLeft ? 1 : 0][0];

        // staging map: f = k*128 + gt ; row = f>>3 ; col4 = f&7
        const int srow  = gt >> 3;               // base row, +16 per k
        const int scol4 = gt & 7;

        float s = 0.0f;
        for (int ch = 0; ch < NCHUNK; ++ch) {
            // right walks chunks forward, left backward
            const int wX = (isLeft ? (NCHUNK - 1 - ch) : ch) * CHUNK;

            // ---- load: LDG.128 -> STS.128 (swizzled, conflict-free) ----
#pragma unroll
            for (int k = 0; k < 8; ++k) {
                int row = srow + k * 16;
                float4 v = *(const float4*)&xbase[(size_t)row * WW + wX + scol4 * 4];
                *(float4*)&tile[slot(row, scol4)] = v;
            }
            bar_group(barid);

            // ---- scan owned row gt, one float4 window at a time ----
            if (!isLeft) {
#pragma unroll
                for (int q = 0; q < 8; ++q) {
                    float4 v = *(float4*)&tile[slot(gt, q)];
                    if (ch == 0 && q == 0) s = v.x;
                    else v.x = s = fmaxf(fmaf(wsc, s, bsc + v.x), 0.0f);
                    v.y = s = fmaxf(fmaf(wsc, s, bsc + v.y), 0.0f);
                    v.z = s = fmaxf(fmaf(wsc, s, bsc + v.z), 0.0f);
                    v.w = s = fmaxf(fmaf(wsc, s, bsc + v.w), 0.0f);
                    if (ch == 0 && q == 0) v.x = s == s ? *(&v.x) : v.x; // keep v.x raw
                    *(float4*)&tile[slot(gt, q)] = v;
                }
            } else {
#pragma unroll
                for (int q = 7; q >= 0; --q) {
                    float4 v = *(float4*)&tile[slot(gt, q)];
                    if (ch == 0 && q == 7) s = v.w;
                    else v.w = s = fmaxf(fmaf(wsc, s, bsc + v.w), 0.0f);
                    v.z = s = fmaxf(fmaf(wsc, s, bsc + v.z), 0.0f);
                    v.y = s = fmaxf(fmaf(wsc, s, bsc + v.y), 0.0f);
                    v.x = s = fmaxf(fmaf(wsc, s, bsc + v.x), 0.0f);
                    *(float4*)&tile[slot(gt, q)] = v;
                }
            }
            bar_group(barid);

            // ---- store: LDS.128 -> STG.128 streaming ----
#pragma unroll
            for (int k = 0; k < 8; ++k) {
                int row = srow + k * 16;
                float4 v = *(float4*)&tile[slot(row, scol4)];
                __stcs((float4*)&obase[(size_t)row * WW + wX + scol4 * 4], v);
            }
            bar_group(barid);   // tile reads done before next chunk overwrites
        }
    }
}

extern "C" void kernel_launch(void* const* d_in, const int* in_sizes, int n_in,
                              void* d_out, int out_size)
{
    const float* x       = (const float*)d_in[0];
    const float* w_up    = (const float*)d_in[1];
    const float* w_right = (const float*)d_in[2];
    const float* w_down  = (const float*)d_in[3];
    const float* w_left  = (const float*)d_in[4];
    const float* b_up    = (const float*)d_in[5];
    const float* b_right = (const float*)d_in[6];
    const float* b_down  = (const float*)d_in[7];
    const float* b_left  = (const float*)d_in[8];
    float* out = (float*)d_out;

    // 512 vertical (256 down + 256 up) + 512 horizontal, interleaved by parity
    irnn_fused_kernel<<<1024, TPB>>>(x,
                                     w_up, b_up, w_right, b_right,
                                     w_down, b_down, w_left, b_left,
                                     out);
}